// round 5
// baseline (speedup 1.0000x reference)
#include <cuda_runtime.h>
#include <cuda_bf16.h>
#include <cstdint>

#define EMB   1024
#define HID   4096
#define NHEADS 16
#define DK    64
#define BATCH 2
#define SEQ   2048
#define ROWS  (BATCH*SEQ)        // 4096
#define LNEPS 1e-6f
#define LOG2E 1.442695041f

// ==================== scratch (device globals) ====================
__device__ float          g_h   [ROWS*EMB];
__device__ __nv_bfloat16  g_lnh [ROWS*EMB];
__device__ __nv_bfloat16  g_lnl [ROWS*EMB];
__device__ __nv_bfloat16  g_qkvh[3*ROWS*EMB];   // [sel][bh][s][d]
__device__ __nv_bfloat16  g_qkvl[3*ROWS*EMB];
__device__ __nv_bfloat16  g_ath [ROWS*EMB];
__device__ __nv_bfloat16  g_atl [ROWS*EMB];
__device__ __nv_bfloat16  g_ffh [ROWS*HID];
__device__ __nv_bfloat16  g_ffl [ROWS*HID];
// transposed split weights [N x K]
__device__ __nv_bfloat16  g_wqkvh[3*EMB*EMB], g_wqkvl[3*EMB*EMB];
__device__ __nv_bfloat16  g_woh[EMB*EMB], g_wol[EMB*EMB];
__device__ __nv_bfloat16  g_f1h[EMB*HID], g_f1l[EMB*HID];
__device__ __nv_bfloat16  g_f2h[EMB*HID], g_f2l[EMB*HID];

// ==================== baseline-PTX helpers ====================
__device__ __forceinline__ uint32_t smem_u32(const void* p) {
    uint32_t a;
    asm("{ .reg .u64 t; cvta.to.shared.u64 t, %1; cvt.u32.u64 %0, t; }" : "=r"(a) : "l"(p));
    return a;
}
__device__ __forceinline__ void cpa16(uint32_t dst, const void* src) {
    asm volatile("cp.async.cg.shared.global [%0], [%1], 16;" :: "r"(dst), "l"(src));
}
__device__ __forceinline__ void ldm4(uint32_t* r, uint32_t addr) {
    asm volatile("ldmatrix.sync.aligned.m8n8.x4.shared.b16 {%0,%1,%2,%3}, [%4];"
                 : "=r"(r[0]), "=r"(r[1]), "=r"(r[2]), "=r"(r[3]) : "r"(addr));
}
__device__ __forceinline__ void ldm4t(uint32_t* r, uint32_t addr) {
    asm volatile("ldmatrix.sync.aligned.m8n8.x4.trans.shared.b16 {%0,%1,%2,%3}, [%4];"
                 : "=r"(r[0]), "=r"(r[1]), "=r"(r[2]), "=r"(r[3]) : "r"(addr));
}
__device__ __forceinline__ void mma_bf16(float* d, const uint32_t* a, const uint32_t* b) {
    asm volatile("mma.sync.aligned.m16n8k16.row.col.f32.bf16.bf16.f32 "
                 "{%0,%1,%2,%3}, {%4,%5,%6,%7}, {%8,%9}, {%0,%1,%2,%3};"
                 : "+f"(d[0]), "+f"(d[1]), "+f"(d[2]), "+f"(d[3])
                 : "r"(a[0]), "r"(a[1]), "r"(a[2]), "r"(a[3]), "r"(b[0]), "r"(b[1]));
}
__device__ __forceinline__ uint32_t packbf(float lo, float hi) {
    uint32_t r;
    asm("cvt.rn.bf16x2.f32 %0, %1, %2;" : "=r"(r) : "f"(hi), "f"(lo));
    return r;
}

// ==================== split-transpose kernels ====================
__global__ void splitT_kernel(const float* __restrict__ W,
                              __nv_bfloat16* __restrict__ Th,
                              __nv_bfloat16* __restrict__ Tl, int K, int N) {
    __shared__ float tile[32][33];
    int n0 = blockIdx.x * 32, k0 = blockIdx.y * 32;
    int tx = threadIdx.x, ty = threadIdx.y;       // 32 x 8
#pragma unroll
    for (int i = 0; i < 32; i += 8)
        tile[ty + i][tx] = W[(size_t)(k0 + ty + i) * N + n0 + tx];
    __syncthreads();
#pragma unroll
    for (int i = 0; i < 32; i += 8) {
        float v = tile[tx][ty + i];
        __nv_bfloat16 h = __float2bfloat16(v);
        float lo = v - __bfloat162float(h);
        size_t o = (size_t)(n0 + ty + i) * K + k0 + tx;
        Th[o] = h;
        Tl[o] = __float2bfloat16(lo);
    }
}
// QKV fused: z selects wq/wk/wv; dst offset z*EMB*EMB
__global__ void splitT_qkv_kernel(const float* __restrict__ Wq, const float* __restrict__ Wk,
                                  const float* __restrict__ Wv,
                                  __nv_bfloat16* __restrict__ Th,
                                  __nv_bfloat16* __restrict__ Tl) {
    __shared__ float tile[32][33];
    const float* W = (blockIdx.z == 0) ? Wq : (blockIdx.z == 1) ? Wk : Wv;
    __nv_bfloat16* Dh = Th + (size_t)blockIdx.z * EMB * EMB;
    __nv_bfloat16* Dl = Tl + (size_t)blockIdx.z * EMB * EMB;
    int n0 = blockIdx.x * 32, k0 = blockIdx.y * 32;
    int tx = threadIdx.x, ty = threadIdx.y;
#pragma unroll
    for (int i = 0; i < 32; i += 8)
        tile[ty + i][tx] = W[(size_t)(k0 + ty + i) * EMB + n0 + tx];
    __syncthreads();
#pragma unroll
    for (int i = 0; i < 32; i += 8) {
        float v = tile[tx][ty + i];
        __nv_bfloat16 h = __float2bfloat16(v);
        float lo = v - __bfloat162float(h);
        size_t o = (size_t)(n0 + ty + i) * EMB + k0 + tx;
        Dh[o] = h;
        Dl[o] = __float2bfloat16(lo);
    }
}

// ==================== LayerNorm -> bf16 hi/lo ====================
__global__ void ln_kernel(const float* __restrict__ x,
                          __nv_bfloat16* __restrict__ yh, __nv_bfloat16* __restrict__ yl,
                          const float* __restrict__ alpha, const float* __restrict__ beta) {
    __shared__ float red[8];
    int row = blockIdx.x;
    int t = threadIdx.x;
    const float* xr = x + (size_t)row * EMB;
    float v[4];
#pragma unroll
    for (int i = 0; i < 4; i++) v[i] = xr[t + 256 * i];
    float s = v[0] + v[1] + v[2] + v[3];
#pragma unroll
    for (int o = 16; o > 0; o >>= 1) s += __shfl_xor_sync(0xffffffffu, s, o);
    if ((t & 31) == 0) red[t >> 5] = s;
    __syncthreads();
    float tot = 0.f;
#pragma unroll
    for (int i = 0; i < 8; i++) tot += red[i];
    float mean = tot * (1.0f / EMB);
    __syncthreads();
    float sq = 0.f;
#pragma unroll
    for (int i = 0; i < 4; i++) { float d = v[i] - mean; sq += d * d; }
#pragma unroll
    for (int o = 16; o > 0; o >>= 1) sq += __shfl_xor_sync(0xffffffffu, sq, o);
    if ((t & 31) == 0) red[t >> 5] = sq;
    __syncthreads();
    float sqt = 0.f;
#pragma unroll
    for (int i = 0; i < 8; i++) sqt += red[i];
    float stdv = sqrtf(sqt * (1.0f / (EMB - 1)));
    float scale = alpha[0] / (stdv + LNEPS);
    float bias = beta[0];
#pragma unroll
    for (int i = 0; i < 4; i++) {
        float y = scale * (v[i] - mean) + bias;
        __nv_bfloat16 h = __float2bfloat16(y);
        size_t o = (size_t)row * EMB + t + 256 * i;
        yh[o] = h;
        yl[o] = __float2bfloat16(y - __bfloat162float(h));
    }
}

// ==================== mma.sync split-bf16 GEMM, 256x128 CTA tile ====================
// C[4096 x N] = A[4096 x K] * B^T   (B stored [N x K], hi/lo pairs)
// 256 threads, 8 warps as 4(m) x 2(n): warp tile 64 x 64 (acc 4x8x4 = 128 regs).
// BK=32 double-buffered via cp.async.
enum { EPI_QKV = 1, EPI_RES = 2, EPI_BIAS_RELU_SPLIT = 3, EPI_BIAS_RES = 4 };

#define ASZ 20480                 // 256 rows * 80 B
#define BSZ 10240                 // 128 rows * 80 B
#define STG (2*ASZ + 2*BSZ)       // 61440 per stage (Ah, Al, Bh, Bl)
#define MGEMM_SMEM (2*STG)        // 122880

template <int EPI>
__global__ __launch_bounds__(256, 1)
void mgemm_kernel(const __nv_bfloat16* __restrict__ Ah, const __nv_bfloat16* __restrict__ Al,
                  const __nv_bfloat16* __restrict__ Bh, const __nv_bfloat16* __restrict__ Bl,
                  int K, int N,
                  float* __restrict__ C, const float* __restrict__ bias,
                  const float* __restrict__ res,
                  __nv_bfloat16* __restrict__ Ch, __nv_bfloat16* __restrict__ Cl) {
    extern __shared__ char sm[];
    const int tid = threadIdx.x;
    const int lane = tid & 31, wid = tid >> 5;
    const int wm = wid >> 1, wn = wid & 1;         // 4 x 2 warps, warp tile 64x64
    const int bx = blockIdx.x, by = blockIdx.y;
    const uint32_t sb = smem_u32(sm);

    const __nv_bfloat16* gA[2] = { Ah + (size_t)(by * 256) * K, Al + (size_t)(by * 256) * K };
    const __nv_bfloat16* gB[2] = { Bh + (size_t)(bx * 128) * K, Bl + (size_t)(bx * 128) * K };

    float acc[4][8][4];
#pragma unroll
    for (int i = 0; i < 4; i++)
#pragma unroll
        for (int j = 0; j < 8; j++)
#pragma unroll
            for (int r = 0; r < 4; r++) acc[i][j][r] = 0.f;

    auto load_chunk = [&](int c, int buf) {
        const size_t koff = (size_t)c * 32;
        const uint32_t st = sb + buf * STG;
        // A: 2 matrices x 256 rows x 4 float4 = 2048 copies
#pragma unroll
        for (int i = 0; i < 8; i++) {
            int id = tid + 256 * i;
            int mat = i >> 2;
            int within = id & 1023;
            int r = within >> 2, cc = within & 3;
            cpa16(st + mat * ASZ + r * 80 + cc * 16,
                  gA[mat] + (size_t)r * K + koff + cc * 8);
        }
        // B: 2 matrices x 128 rows x 4 float4 = 1024 copies
#pragma unroll
        for (int i = 0; i < 4; i++) {
            int id = tid + 256 * i;
            int mat = i >> 1;
            int within = id & 511;
            int r = within >> 2, cc = within & 3;
            cpa16(st + 2 * ASZ + mat * BSZ + r * 80 + cc * 16,
                  gB[mat] + (size_t)r * K + koff + cc * 8);
        }
    };

    const int nch = K >> 5;
    load_chunk(0, 0);
    asm volatile("cp.async.commit_group;" ::: "memory");

    for (int c = 0; c < nch; c++) {
        if (c + 1 < nch) {
            load_chunk(c + 1, (c + 1) & 1);
            asm volatile("cp.async.commit_group;" ::: "memory");
            asm volatile("cp.async.wait_group 1;" ::: "memory");
        } else {
            asm volatile("cp.async.wait_group 0;" ::: "memory");
        }
        __syncthreads();

        const uint32_t base = sb + (c & 1) * STG;
        const char* bufc = sm + (c & 1) * STG;
#pragma unroll
        for (int kk = 0; kk < 2; kk++) {
            const int kb = kk * 32;
            // A fragments (hi + lo) for 4 m16 blocks
            uint32_t ah[4][4], al[4][4];
            const uint32_t arow = base + ((wm * 64 + (lane & 15)) * 80) + kb + ((lane >> 4) << 4);
#pragma unroll
            for (int mb = 0; mb < 4; mb++) {
                ldm4(ah[mb], arow + mb * 16 * 80);
                ldm4(al[mb], arow + ASZ + mb * 16 * 80);
            }
            // B fragments just-in-time per n8 block
#pragma unroll
            for (int nb = 0; nb < 8; nb++) {
                const char* p = bufc + 2 * ASZ
                              + (wn * 64 + nb * 8 + (lane >> 2)) * 80 + kb + (lane & 3) * 4;
                uint32_t bh[2], bl[2];
                bh[0] = *(const uint32_t*)p;
                bh[1] = *(const uint32_t*)(p + 16);
                bl[0] = *(const uint32_t*)(p + BSZ);
                bl[1] = *(const uint32_t*)(p + BSZ + 16);
#pragma unroll
                for (int mb = 0; mb < 4; mb++) {
                    mma_bf16(acc[mb][nb], ah[mb], bh);
                    mma_bf16(acc[mb][nb], al[mb], bh);
                    mma_bf16(acc[mb][nb], ah[mb], bl);
                }
            }
        }
        __syncthreads();
    }

    // ==================== epilogue ====================
    const int g = lane >> 2, cb = (lane & 3) * 2;
#pragma unroll
    for (int mb = 0; mb < 4; mb++) {
#pragma unroll
        for (int hh = 0; hh < 2; hh++) {
            const int row = by * 256 + wm * 64 + mb * 16 + g + hh * 8;
#pragma unroll
            for (int nb = 0; nb < 8; nb++) {
                const int col = bx * 128 + wn * 64 + nb * 8 + cb;
                float v0 = acc[mb][nb][hh * 2 + 0];
                float v1 = acc[mb][nb][hh * 2 + 1];
                if (EPI == EPI_QKV) {
                    int sel = col >> 10, hc = col & 1023;
                    int h_ = hc >> 6, d_ = hc & (DK - 1);
                    int b_ = row >> 11, s_ = row & (SEQ - 1);
                    size_t dst = (size_t)sel * ROWS * EMB
                               + (((size_t)(b_ * NHEADS + h_)) * SEQ + s_) * DK + d_;
                    __nv_bfloat16 h0 = __float2bfloat16(v0);
                    __nv_bfloat16 h1 = __float2bfloat16(v1);
                    Ch[dst] = h0; Ch[dst + 1] = h1;
                    Cl[dst]     = __float2bfloat16(v0 - __bfloat162float(h0));
                    Cl[dst + 1] = __float2bfloat16(v1 - __bfloat162float(h1));
                } else if (EPI == EPI_RES) {
                    size_t o = (size_t)row * N + col;
                    C[o]     = v0 + res[o];
                    C[o + 1] = v1 + res[o + 1];
                } else if (EPI == EPI_BIAS_RELU_SPLIT) {
                    v0 = fmaxf(v0 + bias[col], 0.f);
                    v1 = fmaxf(v1 + bias[col + 1], 0.f);
                    __nv_bfloat16 h0 = __float2bfloat16(v0);
                    __nv_bfloat16 h1 = __float2bfloat16(v1);
                    size_t o = (size_t)row * N + col;
                    Ch[o] = h0; Ch[o + 1] = h1;
                    Cl[o]     = __float2bfloat16(v0 - __bfloat162float(h0));
                    Cl[o + 1] = __float2bfloat16(v1 - __bfloat162float(h1));
                } else { // EPI_BIAS_RES
                    size_t o = (size_t)row * N + col;
                    C[o]     = v0 + bias[col]     + res[o];
                    C[o + 1] = v1 + bias[col + 1] + res[o + 1];
                }
            }
        }
    }
}

// ==================== tensor-core flash attention (unchanged from R4) ====================
#define AT_STRIDE 144
#define AT_QH 0
#define AT_QL 18432
#define AT_KV0 36864
#define AT_MASK 184320
#define ATT_SMEM (184320 + 1024)

__global__ __launch_bounds__(256, 1)
void attn3_kernel(const __nv_bfloat16* __restrict__ QKVh,
                  const __nv_bfloat16* __restrict__ QKVl,
                  const int* __restrict__ mask,
                  __nv_bfloat16* __restrict__ Oh, __nv_bfloat16* __restrict__ Ol) {
    extern __shared__ char sm[];
    const uint32_t sb = smem_u32(sm);
    const int tid = threadIdx.x, lane = tid & 31, w = tid >> 5;
    const int g = lane >> 2, c4 = lane & 3;
    const int qt = blockIdx.x, bh = blockIdx.y;
    const int b = bh >> 4, h = bh & 15;

    const __nv_bfloat16* Qh = QKVh;
    const __nv_bfloat16* Ql = QKVl;
    const __nv_bfloat16* Kh = QKVh + (size_t)ROWS * EMB;
    const __nv_bfloat16* Kl = QKVl + (size_t)ROWS * EMB;
    const __nv_bfloat16* Vh = QKVh + 2 * (size_t)ROWS * EMB;
    const __nv_bfloat16* Vl = QKVl + 2 * (size_t)ROWS * EMB;

    const size_t qoff = ((size_t)bh * SEQ + qt * 128) * DK;
    const size_t kvbase = (size_t)bh * SEQ * DK;

#pragma unroll
    for (int mtx = 0; mtx < 2; mtx++) {
        const __nv_bfloat16* src = mtx ? Ql : Qh;
#pragma unroll
        for (int i = 0; i < 4; i++) {
            int id = tid + 256 * i;
            int r = id >> 3, cc = id & 7;
            cpa16(sb + AT_QH + mtx * 18432 + r * AT_STRIDE + cc * 16,
                  src + qoff + (size_t)r * DK + cc * 8);
        }
    }
    auto load_kv = [&](int kc, int stg) {
        const size_t koff = kvbase + (size_t)kc * 128 * DK;
        const __nv_bfloat16* srcs[4] = { Kh + koff, Kl + koff, Vh + koff, Vl + koff };
#pragma unroll
        for (int mtx = 0; mtx < 4; mtx++) {
#pragma unroll
            for (int i = 0; i < 4; i++) {
                int id = tid + 256 * i;
                int r = id >> 3, cc = id & 7;
                cpa16(sb + AT_KV0 + stg * 73728 + mtx * 18432 + r * AT_STRIDE + cc * 16,
                      srcs[mtx] + (size_t)r * DK + cc * 8);
            }
        }
        if (tid < 32)
            cpa16(sb + AT_MASK + stg * 512 + tid * 16, mask + b * SEQ + kc * 128 + tid * 4);
    };
    load_kv(0, 0);
    asm volatile("cp.async.commit_group;" ::: "memory");
    load_kv(1, 1);
    asm volatile("cp.async.commit_group;" ::: "memory");
    asm volatile("cp.async.wait_group 1;" ::: "memory");
    __syncthreads();

    uint32_t qfh[4][4], qfl[4][4];
    {
        const uint32_t qrow = sb + AT_QH + (w * 16 + (lane & 15)) * AT_STRIDE + ((lane >> 4) << 4);
#pragma unroll
        for (int ks = 0; ks < 4; ks++) {
            ldm4(qfh[ks], qrow + ks * 32);
            ldm4(qfl[ks], qrow + 18432 + ks * 32);
        }
    }

    float accO[8][4];
#pragma unroll
    for (int i = 0; i < 8; i++)
#pragma unroll
        for (int j = 0; j < 4; j++) accO[i][j] = 0.f;
    float m0 = -1e30f, m1 = -1e30f, l0 = 0.f, l1 = 0.f;

    for (int kc = 0; kc < SEQ / 128; kc++) {
        if (kc >= 1 && kc + 1 < SEQ / 128) {
            load_kv(kc + 1, (kc + 1) & 1);
            asm volatile("cp.async.commit_group;" ::: "memory");
            asm volatile("cp.async.wait_group 1;" ::: "memory");
            __syncthreads();
        } else if (kc + 1 == SEQ / 128) {
            asm volatile("cp.async.wait_group 0;" ::: "memory");
            __syncthreads();
        }
        const uint32_t kvb = sb + AT_KV0 + (kc & 1) * 73728;
        const int* msp = (const int*)(sm + AT_MASK + (kc & 1) * 512);

        float s[16][4];
#pragma unroll
        for (int nb = 0; nb < 16; nb++)
#pragma unroll
            for (int j = 0; j < 4; j++) s[nb][j] = 0.f;
#pragma unroll
        for (int ks = 0; ks < 4; ks++) {
#pragma unroll
            for (int np = 0; np < 8; np++) {
                const int grp = lane >> 3;
                const uint32_t baddr = kvb + (np * 16 + (grp >> 1) * 8 + (lane & 7)) * AT_STRIDE
                                     + ks * 32 + (grp & 1) * 16;
                uint32_t bfh[4], bfl[4];
                ldm4(bfh, baddr);
                ldm4(bfl, baddr + 18432);
                mma_bf16(s[np * 2 + 0], qfh[ks], bfh + 0);
                mma_bf16(s[np * 2 + 0], qfl[ks], bfh + 0);
                mma_bf16(s[np * 2 + 0], qfh[ks], bfl + 0);
                mma_bf16(s[np * 2 + 1], qfh[ks], bfh + 2);
                mma_bf16(s[np * 2 + 1], qfl[ks], bfh + 2);
                mma_bf16(s[np * 2 + 1], qfh[ks], bfl + 2);
            }
        }

        float rm0 = -1e30f, rm1 = -1e30f;
#pragma unroll
        for (int nb = 0; nb < 16; nb++) {
            const int col = nb * 8 + c4 * 2;
            const bool ok0 = msp[col] != 0, ok1 = msp[col + 1] != 0;
            s[nb][0] = ok0 ? s[nb][0] * 0.125f : -1e30f;
            s[nb][1] = ok1 ? s[nb][1] * 0.125f : -1e30f;
            s[nb][2] = ok0 ? s[nb][2] * 0.125f : -1e30f;
            s[nb][3] = ok1 ? s[nb][3] * 0.125f : -1e30f;
            rm0 = fmaxf(rm0, fmaxf(s[nb][0], s[nb][1]));
            rm1 = fmaxf(rm1, fmaxf(s[nb][2], s[nb][3]));
        }
        rm0 = fmaxf(rm0, __shfl_xor_sync(0xffffffffu, rm0, 1));
        rm0 = fmaxf(rm0, __shfl_xor_sync(0xffffffffu, rm0, 2));
        rm1 = fmaxf(rm1, __shfl_xor_sync(0xffffffffu, rm1, 1));
        rm1 = fmaxf(rm1, __shfl_xor_sync(0xffffffffu, rm1, 2));
        const float mn0 = fmaxf(m0, rm0), mn1 = fmaxf(m1, rm1);
        const float al0 = exp2f((m0 - mn0) * LOG2E);
        const float al1 = exp2f((m1 - mn1) * LOG2E);
        m0 = mn0; m1 = mn1;
        float rs0 = 0.f, rs1 = 0.f;
#pragma unroll
        for (int nb = 0; nb < 16; nb++) {
            s[nb][0] = exp2f((s[nb][0] - mn0) * LOG2E);
            s[nb][1] = exp2f((s[nb][1] - mn0) * LOG2E);
            s[nb][2] = exp2f((s[nb][2] - mn1) * LOG2E);
            s[nb][3] = exp2f((s[nb][3] - mn1) * LOG2E);
            rs0 += s[nb][0] + s[nb][1];
            rs1 += s[nb][2] + s[nb][3];
        }
        rs0 += __shfl_xor_sync(0xffffffffu, rs0, 1);
        rs0 += __shfl_xor_sync(0xffffffffu, rs0, 2);
        rs1 += __shfl_xor_sync(0xffffffffu, rs1, 1);
        rs1 += __shfl_xor_sync(0xffffffffu, rs1, 2);
        l0 = l0 * al0 + rs0;
        l1 = l1 * al1 + rs1;
#pragma unroll
        for (int dnb = 0; dnb < 8; dnb++) {
            accO[dnb][0] *= al0; accO[dnb][1] *= al0;
            accO[dnb][2] *= al1; accO[dnb][3] *= al1;
        }

#pragma unroll
        for (int ks = 0; ks < 8; ks++) {
            float e[8] = { s[2*ks][0], s[2*ks][1], s[2*ks][2], s[2*ks][3],
                           s[2*ks+1][0], s[2*ks+1][1], s[2*ks+1][2], s[2*ks+1][3] };
            float eh[8], el[8];
#pragma unroll
            for (int i = 0; i < 8; i++) {
                __nv_bfloat16 hb = __float2bfloat16(e[i]);
                eh[i] = __bfloat162float(hb);
                el[i] = e[i] - eh[i];
            }
            uint32_t pah[4] = { packbf(eh[0], eh[1]), packbf(eh[2], eh[3]),
                                packbf(eh[4], eh[5]), packbf(eh[6], eh[7]) };
            uint32_t pal[4] = { packbf(el[0], el[1]), packbf(el[2], el[3]),
                                packbf(el[4], el[5]), packbf(el[6], el[7]) };
#pragma unroll
            for (int dp = 0; dp < 4; dp++) {
                const int grp = lane >> 3;
                const uint32_t vaddr = kvb + 36864
                                     + (ks * 16 + (grp & 1) * 8 + (lane & 7)) * AT_STRIDE
                                     + dp * 32 + (grp >> 1) * 16;
                uint32_t vfh[4], vfl[4];
                ldm4t(vfh, vaddr);
                ldm4t(vfl, vaddr + 18432);
                mma_bf16(accO[dp * 2 + 0], pah, vfh + 0);
                mma_bf16(accO[dp * 2 + 0], pal, vfh + 0);
                mma_bf16(accO[dp * 2 + 0], pah, vfl + 0);
                mma_bf16(accO[dp * 2 + 1], pah, vfh + 2);
                mma_bf16(accO[dp * 2 + 1], pal, vfh + 2);
                mma_bf16(accO[dp * 2 + 1], pah, vfl + 2);
            }
        }
        if (kc + 1 < SEQ / 128) __syncthreads();
    }

    const float inv0 = 1.f / l0, inv1 = 1.f / l1;
    const int s0 = qt * 128 + w * 16 + g;
    const size_t r0 = ((size_t)b * SEQ + s0) * EMB + h * DK;
    const size_t r1 = ((size_t)b * SEQ + s0 + 8) * EMB + h * DK;
#pragma unroll
    for (int dnb = 0; dnb < 8; dnb++) {
        const int col = dnb * 8 + c4 * 2;
        float v0 = accO[dnb][0] * inv0, v1 = accO[dnb][1] * inv0;
        float v2 = accO[dnb][2] * inv1, v3 = accO[dnb][3] * inv1;
        __nv_bfloat16 h0 = __float2bfloat16(v0), h1 = __float2bfloat16(v1);
        __nv_bfloat16 h2 = __float2bfloat16(v2), h3 = __float2bfloat16(v3);
        *(uint32_t*)(Oh + r0 + col) = ((uint32_t)__bfloat16_as_ushort(h1) << 16) | __bfloat16_as_ushort(h0);
        *(uint32_t*)(Oh + r1 + col) = ((uint32_t)__bfloat16_as_ushort(h3) << 16) | __bfloat16_as_ushort(h2);
        __nv_bfloat16 q0 = __float2bfloat16(v0 - __bfloat162float(h0));
        __nv_bfloat16 q1 = __float2bfloat16(v1 - __bfloat162float(h1));
        __nv_bfloat16 q2 = __float2bfloat16(v2 - __bfloat162float(h2));
        __nv_bfloat16 q3 = __float2bfloat16(v3 - __bfloat162float(h3));
        *(uint32_t*)(Ol + r0 + col) = ((uint32_t)__bfloat16_as_ushort(q1) << 16) | __bfloat16_as_ushort(q0);
        *(uint32_t*)(Ol + r1 + col) = ((uint32_t)__bfloat16_as_ushort(q3) << 16) | __bfloat16_as_ushort(q2);
    }
}

// ==================== launch ====================
extern "C" void kernel_launch(void* const* d_in, const int* in_sizes, int n_in,
                              void* d_out, int out_size) {
    const float* x    = (const float*)d_in[0];
    const int*   mask = (const int*)  d_in[1];
    const float* wq   = (const float*)d_in[2];
    const float* wk   = (const float*)d_in[3];
    const float* wv   = (const float*)d_in[4];
    const float* wo   = (const float*)d_in[5];
    const float* ff1w = (const float*)d_in[6];
    const float* ff1b = (const float*)d_in[7];
    const float* ff2w = (const float*)d_in[8];
    const float* ff2b = (const float*)d_in[9];
    const float* ln1a = (const float*)d_in[10];
    const float* ln1b = (const float*)d_in[11];
    const float* ln2a = (const float*)d_in[12];
    const float* ln2b = (const float*)d_in[13];
    float* out = (float*)d_out;

    float *hb;
    __nv_bfloat16 *lnh, *lnl, *qkvh, *qkvl, *ath, *atl, *ffh, *ffl;
    __nv_bfloat16 *wqkvh, *wqkvl, *woh, *wol, *f1h, *f1l, *f2h, *f2l;
    cudaGetSymbolAddress((void**)&hb, g_h);
    cudaGetSymbolAddress((void**)&lnh, g_lnh);
    cudaGetSymbolAddress((void**)&lnl, g_lnl);
    cudaGetSymbolAddress((void**)&qkvh, g_qkvh);
    cudaGetSymbolAddress((void**)&qkvl, g_qkvl);
    cudaGetSymbolAddress((void**)&ath, g_ath);
    cudaGetSymbolAddress((void**)&atl, g_atl);
    cudaGetSymbolAddress((void**)&ffh, g_ffh);
    cudaGetSymbolAddress((void**)&ffl, g_ffl);
    cudaGetSymbolAddress((void**)&wqkvh, g_wqkvh);
    cudaGetSymbolAddress((void**)&wqkvl, g_wqkvl);
    cudaGetSymbolAddress((void**)&woh, g_woh); cudaGetSymbolAddress((void**)&wol, g_wol);
    cudaGetSymbolAddress((void**)&f1h, g_f1h); cudaGetSymbolAddress((void**)&f1l, g_f1l);
    cudaGetSymbolAddress((void**)&f2h, g_f2h); cudaGetSymbolAddress((void**)&f2l, g_f2l);

    cudaFuncSetAttribute(mgemm_kernel<EPI_QKV>,             cudaFuncAttributeMaxDynamicSharedMemorySize, MGEMM_SMEM);
    cudaFuncSetAttribute(mgemm_kernel<EPI_RES>,             cudaFuncAttributeMaxDynamicSharedMemorySize, MGEMM_SMEM);
    cudaFuncSetAttribute(mgemm_kernel<EPI_BIAS_RELU_SPLIT>, cudaFuncAttributeMaxDynamicSharedMemorySize, MGEMM_SMEM);
    cudaFuncSetAttribute(mgemm_kernel<EPI_BIAS_RES>,        cudaFuncAttributeMaxDynamicSharedMemorySize, MGEMM_SMEM);
    cudaFuncSetAttribute(attn3_kernel,                      cudaFuncAttributeMaxDynamicSharedMemorySize, ATT_SMEM);

    dim3 tb(32, 8);
    // Launch order arranged so the QKV mgemm is launch index 5 (ncu -s 5 -c 1 profiles it).
    splitT_qkv_kernel<<<dim3(32, 32, 3), tb>>>(wq, wk, wv, wqkvh, wqkvl);          // 0
    splitT_kernel<<<dim3(32, 32), tb>>>(wo, woh, wol, EMB, EMB);                    // 1
    splitT_kernel<<<dim3(128, 32), tb>>>(ff1w, f1h, f1l, EMB, HID);                 // 2
    splitT_kernel<<<dim3(32, 128), tb>>>(ff2w, f2h, f2l, HID, EMB);                 // 3
    ln_kernel<<<ROWS, 256>>>(x, lnh, lnl, ln1a, ln1b);                              // 4

    dim3 gQKV(3 * EMB / 128, ROWS / 256); // (24,16)
    dim3 gP(EMB / 128, ROWS / 256);       // (8,16)
    dim3 gF(HID / 128, ROWS / 256);       // (32,16)

    mgemm_kernel<EPI_QKV><<<gQKV, 256, MGEMM_SMEM>>>(lnh, lnl, wqkvh, wqkvl, EMB, 3*EMB, nullptr, nullptr, nullptr, qkvh, qkvl);  // 5 (profiled)
    attn3_kernel<<<dim3(SEQ / 128, BATCH * NHEADS), 256, ATT_SMEM>>>(qkvh, qkvl, mask, ath, atl);
    mgemm_kernel<EPI_RES><<<gP, 256, MGEMM_SMEM>>>(ath, atl, woh, wol, EMB, EMB, hb, nullptr, x, nullptr, nullptr);
    ln_kernel<<<ROWS, 256>>>(hb, lnh, lnl, ln2a, ln2b);
    mgemm_kernel<EPI_BIAS_RELU_SPLIT><<<gF, 256, MGEMM_SMEM>>>(lnh, lnl, f1h, f1l, EMB, HID, nullptr, ff1b, nullptr, ffh, ffl);
    mgemm_kernel<EPI_BIAS_RES><<<gP, 256, MGEMM_SMEM>>>(ffh, ffl, f2h, f2l, HID, EMB, out, ff2b, hb, nullptr, nullptr);
}

// round 15
// speedup vs baseline: 1.1163x; 1.1163x over previous
#include <cuda_runtime.h>
#include <cuda_bf16.h>
#include <cstdint>

#define EMB   1024
#define HID   4096
#define NHEADS 16
#define DK    64
#define BATCH 2
#define SEQ   2048
#define ROWS  (BATCH*SEQ)        // 4096
#define LNEPS 1e-6f
#define LOG2E 1.442695041f

// ==================== scratch (device globals) ====================
__device__ float          g_h   [ROWS*EMB];
__device__ __nv_bfloat16  g_lnh [ROWS*EMB];
__device__ __nv_bfloat16  g_lnl [ROWS*EMB];
__device__ __nv_bfloat16  g_qkvh[3*ROWS*EMB];   // [sel][bh][s][d]
__device__ __nv_bfloat16  g_qkvl[3*ROWS*EMB];
__device__ __nv_bfloat16  g_ath [ROWS*EMB];
__device__ __nv_bfloat16  g_atl [ROWS*EMB];
__device__ __nv_bfloat16  g_ffh [ROWS*HID];
__device__ __nv_bfloat16  g_ffl [ROWS*HID];
// transposed split weights [N x K]
__device__ __nv_bfloat16  g_wqkvh[3*EMB*EMB], g_wqkvl[3*EMB*EMB];
__device__ __nv_bfloat16  g_woh[EMB*EMB], g_wol[EMB*EMB];
__device__ __nv_bfloat16  g_f1h[EMB*HID], g_f1l[EMB*HID];
__device__ __nv_bfloat16  g_f2h[EMB*HID], g_f2l[EMB*HID];

// ==================== baseline-PTX helpers ====================
__device__ __forceinline__ uint32_t smem_u32(const void* p) {
    uint32_t a;
    asm("{ .reg .u64 t; cvta.to.shared.u64 t, %1; cvt.u32.u64 %0, t; }" : "=r"(a) : "l"(p));
    return a;
}
__device__ __forceinline__ void cpa16(uint32_t dst, const void* src) {
    asm volatile("cp.async.cg.shared.global [%0], [%1], 16;" :: "r"(dst), "l"(src));
}
__device__ __forceinline__ void ldm4(uint32_t* r, uint32_t addr) {
    asm volatile("ldmatrix.sync.aligned.m8n8.x4.shared.b16 {%0,%1,%2,%3}, [%4];"
                 : "=r"(r[0]), "=r"(r[1]), "=r"(r[2]), "=r"(r[3]) : "r"(addr));
}
__device__ __forceinline__ void ldm4t(uint32_t* r, uint32_t addr) {
    asm volatile("ldmatrix.sync.aligned.m8n8.x4.trans.shared.b16 {%0,%1,%2,%3}, [%4];"
                 : "=r"(r[0]), "=r"(r[1]), "=r"(r[2]), "=r"(r[3]) : "r"(addr));
}
__device__ __forceinline__ void mma_bf16(float* d, const uint32_t* a, const uint32_t* b) {
    asm volatile("mma.sync.aligned.m16n8k16.row.col.f32.bf16.bf16.f32 "
                 "{%0,%1,%2,%3}, {%4,%5,%6,%7}, {%8,%9}, {%0,%1,%2,%3};"
                 : "+f"(d[0]), "+f"(d[1]), "+f"(d[2]), "+f"(d[3])
                 : "r"(a[0]), "r"(a[1]), "r"(a[2]), "r"(a[3]), "r"(b[0]), "r"(b[1]));
}
__device__ __forceinline__ uint32_t packbf(float lo, float hi) {
    uint32_t r;
    asm("cvt.rn.bf16x2.f32 %0, %1, %2;" : "=r"(r) : "f"(hi), "f"(lo));
    return r;
}

// ==================== split-transpose kernels ====================
__global__ void splitT_kernel(const float* __restrict__ W,
                              __nv_bfloat16* __restrict__ Th,
                              __nv_bfloat16* __restrict__ Tl, int K, int N) {
    __shared__ float tile[32][33];
    int n0 = blockIdx.x * 32, k0 = blockIdx.y * 32;
    int tx = threadIdx.x, ty = threadIdx.y;       // 32 x 8
#pragma unroll
    for (int i = 0; i < 32; i += 8)
        tile[ty + i][tx] = W[(size_t)(k0 + ty + i) * N + n0 + tx];
    __syncthreads();
#pragma unroll
    for (int i = 0; i < 32; i += 8) {
        float v = tile[tx][ty + i];
        __nv_bfloat16 h = __float2bfloat16(v);
        float lo = v - __bfloat162float(h);
        size_t o = (size_t)(n0 + ty + i) * K + k0 + tx;
        Th[o] = h;
        Tl[o] = __float2bfloat16(lo);
    }
}
__global__ void splitT_qkv_kernel(const float* __restrict__ Wq, const float* __restrict__ Wk,
                                  const float* __restrict__ Wv,
                                  __nv_bfloat16* __restrict__ Th,
                                  __nv_bfloat16* __restrict__ Tl) {
    __shared__ float tile[32][33];
    const float* W = (blockIdx.z == 0) ? Wq : (blockIdx.z == 1) ? Wk : Wv;
    __nv_bfloat16* Dh = Th + (size_t)blockIdx.z * EMB * EMB;
    __nv_bfloat16* Dl = Tl + (size_t)blockIdx.z * EMB * EMB;
    int n0 = blockIdx.x * 32, k0 = blockIdx.y * 32;
    int tx = threadIdx.x, ty = threadIdx.y;
#pragma unroll
    for (int i = 0; i < 32; i += 8)
        tile[ty + i][tx] = W[(size_t)(k0 + ty + i) * EMB + n0 + tx];
    __syncthreads();
#pragma unroll
    for (int i = 0; i < 32; i += 8) {
        float v = tile[tx][ty + i];
        __nv_bfloat16 h = __float2bfloat16(v);
        float lo = v - __bfloat162float(h);
        size_t o = (size_t)(n0 + ty + i) * EMB + k0 + tx;
        Dh[o] = h;
        Dl[o] = __float2bfloat16(lo);
    }
}

// ==================== LayerNorm -> bf16 hi/lo ====================
__global__ void ln_kernel(const float* __restrict__ x,
                          __nv_bfloat16* __restrict__ yh, __nv_bfloat16* __restrict__ yl,
                          const float* __restrict__ alpha, const float* __restrict__ beta) {
    __shared__ float red[8];
    int row = blockIdx.x;
    int t = threadIdx.x;
    const float* xr = x + (size_t)row * EMB;
    float v[4];
#pragma unroll
    for (int i = 0; i < 4; i++) v[i] = xr[t + 256 * i];
    float s = v[0] + v[1] + v[2] + v[3];
#pragma unroll
    for (int o = 16; o > 0; o >>= 1) s += __shfl_xor_sync(0xffffffffu, s, o);
    if ((t & 31) == 0) red[t >> 5] = s;
    __syncthreads();
    float tot = 0.f;
#pragma unroll
    for (int i = 0; i < 8; i++) tot += red[i];
    float mean = tot * (1.0f / EMB);
    __syncthreads();
    float sq = 0.f;
#pragma unroll
    for (int i = 0; i < 4; i++) { float d = v[i] - mean; sq += d * d; }
#pragma unroll
    for (int o = 16; o > 0; o >>= 1) sq += __shfl_xor_sync(0xffffffffu, sq, o);
    if ((t & 31) == 0) red[t >> 5] = sq;
    __syncthreads();
    float sqt = 0.f;
#pragma unroll
    for (int i = 0; i < 8; i++) sqt += red[i];
    float stdv = sqrtf(sqt * (1.0f / (EMB - 1)));
    float scale = alpha[0] / (stdv + LNEPS);
    float bias = beta[0];
#pragma unroll
    for (int i = 0; i < 4; i++) {
        float y = scale * (v[i] - mean) + bias;
        __nv_bfloat16 h = __float2bfloat16(y);
        size_t o = (size_t)row * EMB + t + 256 * i;
        yh[o] = h;
        yl[o] = __float2bfloat16(y - __bfloat162float(h));
    }
}

// ==================== mma.sync split-bf16 GEMM (R4 true known-good) ====================
enum { EPI_QKV = 1, EPI_RES = 2, EPI_BIAS_RELU_SPLIT = 3, EPI_BIAS_RES = 4 };

#define TSTRIDE   10240            // 128 rows * 80B
#define BUFSTRIDE (4*TSTRIDE)      // Ah, Al, Bh, Bl
#define MGEMM_SMEM (2*BUFSTRIDE)   // 81920 B

template <int EPI>
__global__ __launch_bounds__(256, 2)
void mgemm_kernel(const __nv_bfloat16* __restrict__ Ah, const __nv_bfloat16* __restrict__ Al,
                  const __nv_bfloat16* __restrict__ Bh, const __nv_bfloat16* __restrict__ Bl,
                  int K, int N,
                  float* __restrict__ C, const float* __restrict__ bias,
                  const float* __restrict__ res,
                  __nv_bfloat16* __restrict__ Ch, __nv_bfloat16* __restrict__ Cl) {
    extern __shared__ char sm[];
    const int tid = threadIdx.x;
    const int lane = tid & 31, wid = tid >> 5;
    const int wm = wid >> 2, wn = wid & 3;
    const int bx = blockIdx.x, by = blockIdx.y;
    const uint32_t sb = smem_u32(sm);

    const __nv_bfloat16* gm[4] = {
        Ah + (size_t)(by * 128) * K, Al + (size_t)(by * 128) * K,
        Bh + (size_t)(bx * 128) * K, Bl + (size_t)(bx * 128) * K };

    float acc[4][4][4];
#pragma unroll
    for (int i = 0; i < 4; i++)
#pragma unroll
        for (int j = 0; j < 4; j++)
#pragma unroll
            for (int r = 0; r < 4; r++) acc[i][j][r] = 0.f;

    // CORRECT BK=32 loader: 64 B per 80-B row, 512 copies per matrix.
    auto load_chunk = [&](int c, int buf) {
        const size_t koff = (size_t)c * 32;
#pragma unroll
        for (int tl = 0; tl < 4; tl++) {
#pragma unroll
            for (int i = 0; i < 2; i++) {
                int id = tid + 256 * i;
                int r = id >> 2, cc = id & 3;
                cpa16(sb + (uint32_t)buf * BUFSTRIDE + (uint32_t)tl * TSTRIDE + r * 80 + cc * 16,
                      gm[tl] + (size_t)r * K + koff + cc * 8);
            }
        }
    };

    const int nch = K >> 5;
    load_chunk(0, 0);
    asm volatile("cp.async.commit_group;" ::: "memory");

    for (int c = 0; c < nch; c++) {
        if (c + 1 < nch) {
            load_chunk(c + 1, (c + 1) & 1);
            asm volatile("cp.async.commit_group;" ::: "memory");
            asm volatile("cp.async.wait_group 1;" ::: "memory");
        } else {
            asm volatile("cp.async.wait_group 0;" ::: "memory");
        }
        __syncthreads();

        const uint32_t base = sb + (c & 1) * BUFSTRIDE;
        const char* bufc = sm + (c & 1) * BUFSTRIDE;
#pragma unroll
        for (int kk = 0; kk < 2; kk++) {
            const int kb = kk * 32;
            // ---- A hi fragments via ldmatrix ----
            uint32_t ah[4][4], al4[4][4];
            const uint32_t arow = base + ((wm * 64 + (lane & 15)) * 80) + kb + ((lane >> 4) << 4);
#pragma unroll
            for (int mb = 0; mb < 4; mb++) ldm4(ah[mb], arow + mb * 16 * 80);
            // ---- B hi fragments via plain LDS.32 ----
            uint32_t bh[4][2], bl[4][2];
#pragma unroll
            for (int nb = 0; nb < 4; nb++) {
                const char* p = bufc + 2 * TSTRIDE
                              + (wn * 32 + nb * 8 + (lane >> 2)) * 80 + kb + (lane & 3) * 4;
                bh[nb][0] = *(const uint32_t*)p;
                bh[nb][1] = *(const uint32_t*)(p + 16);
            }
            // pass 1: hi * hi
#pragma unroll
            for (int mb = 0; mb < 4; mb++)
#pragma unroll
                for (int nb = 0; nb < 4; nb++) mma_bf16(acc[mb][nb], ah[mb], bh[nb]);
            // ---- A lo ----
#pragma unroll
            for (int mb = 0; mb < 4; mb++) ldm4(al4[mb], arow + TSTRIDE + mb * 16 * 80);
            // pass 2: lo * hi
#pragma unroll
            for (int mb = 0; mb < 4; mb++)
#pragma unroll
                for (int nb = 0; nb < 4; nb++) mma_bf16(acc[mb][nb], al4[mb], bh[nb]);
            // ---- B lo ----
#pragma unroll
            for (int nb = 0; nb < 4; nb++) {
                const char* p = bufc + 3 * TSTRIDE
                              + (wn * 32 + nb * 8 + (lane >> 2)) * 80 + kb + (lane & 3) * 4;
                bl[nb][0] = *(const uint32_t*)p;
                bl[nb][1] = *(const uint32_t*)(p + 16);
            }
            // pass 3: hi * lo
#pragma unroll
            for (int mb = 0; mb < 4; mb++)
#pragma unroll
                for (int nb = 0; nb < 4; nb++) mma_bf16(acc[mb][nb], ah[mb], bl[nb]);
        }
        __syncthreads();
    }

    // ==================== epilogue ====================
    const int g = lane >> 2, cb = (lane & 3) * 2;
#pragma unroll
    for (int mb = 0; mb < 4; mb++) {
#pragma unroll
        for (int hh = 0; hh < 2; hh++) {
            const int row = by * 128 + wm * 64 + mb * 16 + g + hh * 8;
#pragma unroll
            for (int nb = 0; nb < 4; nb++) {
                const int col = bx * 128 + wn * 32 + nb * 8 + cb;
                float v0 = acc[mb][nb][hh * 2 + 0];
                float v1 = acc[mb][nb][hh * 2 + 1];
                if (EPI == EPI_QKV) {
                    int sel = col >> 10, hc = col & 1023;
                    int h_ = hc >> 6, d_ = hc & (DK - 1);
                    int b_ = row >> 11, s_ = row & (SEQ - 1);
                    size_t dst = (size_t)sel * ROWS * EMB
                               + (((size_t)(b_ * NHEADS + h_)) * SEQ + s_) * DK + d_;
                    __nv_bfloat16 h0 = __float2bfloat16(v0);
                    __nv_bfloat16 h1 = __float2bfloat16(v1);
                    Ch[dst] = h0; Ch[dst + 1] = h1;
                    Cl[dst]     = __float2bfloat16(v0 - __bfloat162float(h0));
                    Cl[dst + 1] = __float2bfloat16(v1 - __bfloat162float(h1));
                } else if (EPI == EPI_RES) {
                    size_t o = (size_t)row * N + col;
                    C[o]     = v0 + res[o];
                    C[o + 1] = v1 + res[o + 1];
                } else if (EPI == EPI_BIAS_RELU_SPLIT) {
                    v0 = fmaxf(v0 + bias[col], 0.f);
                    v1 = fmaxf(v1 + bias[col + 1], 0.f);
                    __nv_bfloat16 h0 = __float2bfloat16(v0);
                    __nv_bfloat16 h1 = __float2bfloat16(v1);
                    size_t o = (size_t)row * N + col;
                    Ch[o] = h0; Ch[o + 1] = h1;
                    Cl[o]     = __float2bfloat16(v0 - __bfloat162float(h0));
                    Cl[o + 1] = __float2bfloat16(v1 - __bfloat162float(h1));
                } else { // EPI_BIAS_RES
                    size_t o = (size_t)row * N + col;
                    C[o]     = v0 + bias[col]     + res[o];
                    C[o + 1] = v1 + bias[col + 1] + res[o + 1];
                }
            }
        }
    }
}

// ==================== tensor-core flash attention (R4 pipeline; PV pure-bf16) ====================
#define AT_STRIDE 144
#define AT_QH 0
#define AT_QL 18432
#define AT_KV0 36864
#define AT_MASK 184320
#define ATT_SMEM (184320 + 1024)

__global__ __launch_bounds__(256, 1)
void attn3_kernel(const __nv_bfloat16* __restrict__ QKVh,
                  const __nv_bfloat16* __restrict__ QKVl,
                  const int* __restrict__ mask,
                  __nv_bfloat16* __restrict__ Oh, __nv_bfloat16* __restrict__ Ol) {
    extern __shared__ char sm[];
    const uint32_t sb = smem_u32(sm);
    const int tid = threadIdx.x, lane = tid & 31, w = tid >> 5;
    const int g = lane >> 2, c4 = lane & 3;
    const int qt = blockIdx.x, bh = blockIdx.y;
    const int b = bh >> 4, h = bh & 15;

    const __nv_bfloat16* Qh = QKVh;
    const __nv_bfloat16* Ql = QKVl;
    const __nv_bfloat16* Kh = QKVh + (size_t)ROWS * EMB;
    const __nv_bfloat16* Kl = QKVl + (size_t)ROWS * EMB;
    const __nv_bfloat16* Vh = QKVh + 2 * (size_t)ROWS * EMB;

    const size_t qoff = ((size_t)bh * SEQ + qt * 128) * DK;
    const size_t kvbase = (size_t)bh * SEQ * DK;

#pragma unroll
    for (int mtx = 0; mtx < 2; mtx++) {
        const __nv_bfloat16* src = mtx ? Ql : Qh;
#pragma unroll
        for (int i = 0; i < 4; i++) {
            int id = tid + 256 * i;
            int r = id >> 3, cc = id & 7;
            cpa16(sb + AT_QH + mtx * 18432 + r * AT_STRIDE + cc * 16,
                  src + qoff + (size_t)r * DK + cc * 8);
        }
    }
    // KV: only Kh, Kl, Vh (PV pure bf16; Vl never loaded)
    auto load_kv = [&](int kc, int stg) {
        const size_t koff = kvbase + (size_t)kc * 128 * DK;
        const __nv_bfloat16* srcs[3] = { Kh + koff, Kl + koff, Vh + koff };
#pragma unroll
        for (int mtx = 0; mtx < 3; mtx++) {
#pragma unroll
            for (int i = 0; i < 4; i++) {
                int id = tid + 256 * i;
                int r = id >> 3, cc = id & 7;
                cpa16(sb + AT_KV0 + stg * 73728 + mtx * 18432 + r * AT_STRIDE + cc * 16,
                      srcs[mtx] + (size_t)r * DK + cc * 8);
            }
        }
        if (tid < 32)
            cpa16(sb + AT_MASK + stg * 512 + tid * 16, mask + b * SEQ + kc * 128 + tid * 4);
    };
    load_kv(0, 0);
    asm volatile("cp.async.commit_group;" ::: "memory");
    load_kv(1, 1);
    asm volatile("cp.async.commit_group;" ::: "memory");
    asm volatile("cp.async.wait_group 1;" ::: "memory");
    __syncthreads();

    uint32_t qfh[4][4], qfl[4][4];
    {
        const uint32_t qrow = sb + AT_QH + (w * 16 + (lane & 15)) * AT_STRIDE + ((lane >> 4) << 4);
#pragma unroll
        for (int ks = 0; ks < 4; ks++) {
            ldm4(qfh[ks], qrow + ks * 32);
            ldm4(qfl[ks], qrow + 18432 + ks * 32);
        }
    }

    float accO[8][4];
#pragma unroll
    for (int i = 0; i < 8; i++)
#pragma unroll
        for (int j = 0; j < 4; j++) accO[i][j] = 0.f;
    float m0 = -1e30f, m1 = -1e30f, l0 = 0.f, l1 = 0.f;

    for (int kc = 0; kc < SEQ / 128; kc++) {
        if (kc >= 1 && kc + 1 < SEQ / 128) {
            load_kv(kc + 1, (kc + 1) & 1);
            asm volatile("cp.async.commit_group;" ::: "memory");
            asm volatile("cp.async.wait_group 1;" ::: "memory");
            __syncthreads();
        } else if (kc + 1 == SEQ / 128) {
            asm volatile("cp.async.wait_group 0;" ::: "memory");
            __syncthreads();
        }
        const uint32_t kvb = sb + AT_KV0 + (kc & 1) * 73728;
        const int* msp = (const int*)(sm + AT_MASK + (kc & 1) * 512);

        float s[16][4];
#pragma unroll
        for (int nb = 0; nb < 16; nb++)
#pragma unroll
            for (int j = 0; j < 4; j++) s[nb][j] = 0.f;
#pragma unroll
        for (int ks = 0; ks < 4; ks++) {
#pragma unroll
            for (int np = 0; np < 8; np++) {
                const int grp = lane >> 3;
                const uint32_t baddr = kvb + (np * 16 + (grp >> 1) * 8 + (lane & 7)) * AT_STRIDE
                                     + ks * 32 + (grp & 1) * 16;
                uint32_t bfh[4], bfl[4];
                ldm4(bfh, baddr);
                ldm4(bfl, baddr + 18432);
                mma_bf16(s[np * 2 + 0], qfh[ks], bfh + 0);
                mma_bf16(s[np * 2 + 0], qfl[ks], bfh + 0);
                mma_bf16(s[np * 2 + 0], qfh[ks], bfl + 0);
                mma_bf16(s[np * 2 + 1], qfh[ks], bfh + 2);
                mma_bf16(s[np * 2 + 1], qfl[ks], bfh + 2);
                mma_bf16(s[np * 2 + 1], qfh[ks], bfl + 2);
            }
        }

        float rm0 = -1e30f, rm1 = -1e30f;
#pragma unroll
        for (int nb = 0; nb < 16; nb++) {
            const int col = nb * 8 + c4 * 2;
            const bool ok0 = msp[col] != 0, ok1 = msp[col + 1] != 0;
            s[nb][0] = ok0 ? s[nb][0] * 0.125f : -1e30f;
            s[nb][1] = ok1 ? s[nb][1] * 0.125f : -1e30f;
            s[nb][2] = ok0 ? s[nb][2] * 0.125f : -1e30f;
            s[nb][3] = ok1 ? s[nb][3] * 0.125f : -1e30f;
            rm0 = fmaxf(rm0, fmaxf(s[nb][0], s[nb][1]));
            rm1 = fmaxf(rm1, fmaxf(s[nb][2], s[nb][3]));
        }
        rm0 = fmaxf(rm0, __shfl_xor_sync(0xffffffffu, rm0, 1));
        rm0 = fmaxf(rm0, __shfl_xor_sync(0xffffffffu, rm0, 2));
        rm1 = fmaxf(rm1, __shfl_xor_sync(0xffffffffu, rm1, 1));
        rm1 = fmaxf(rm1, __shfl_xor_sync(0xffffffffu, rm1, 2));
        const float mn0 = fmaxf(m0, rm0), mn1 = fmaxf(m1, rm1);
        const float al0 = exp2f((m0 - mn0) * LOG2E);
        const float al1 = exp2f((m1 - mn1) * LOG2E);
        m0 = mn0; m1 = mn1;
        float rs0 = 0.f, rs1 = 0.f;
#pragma unroll
        for (int nb = 0; nb < 16; nb++) {
            s[nb][0] = exp2f((s[nb][0] - mn0) * LOG2E);
            s[nb][1] = exp2f((s[nb][1] - mn0) * LOG2E);
            s[nb][2] = exp2f((s[nb][2] - mn1) * LOG2E);
            s[nb][3] = exp2f((s[nb][3] - mn1) * LOG2E);
            rs0 += s[nb][0] + s[nb][1];
            rs1 += s[nb][2] + s[nb][3];
        }
        rs0 += __shfl_xor_sync(0xffffffffu, rs0, 1);
        rs0 += __shfl_xor_sync(0xffffffffu, rs0, 2);
        rs1 += __shfl_xor_sync(0xffffffffu, rs1, 1);
        rs1 += __shfl_xor_sync(0xffffffffu, rs1, 2);
        l0 = l0 * al0 + rs0;
        l1 = l1 * al1 + rs1;
#pragma unroll
        for (int dnb = 0; dnb < 8; dnb++) {
            accO[dnb][0] *= al0; accO[dnb][1] *= al0;
            accO[dnb][2] *= al1; accO[dnb][3] *= al1;
        }

        // ---- PV: pure bf16 ----
#pragma unroll
        for (int ks = 0; ks < 8; ks++) {
            uint32_t pah[4] = { packbf(s[2*ks][0],   s[2*ks][1]),
                                packbf(s[2*ks][2],   s[2*ks][3]),
                                packbf(s[2*ks+1][0], s[2*ks+1][1]),
                                packbf(s[2*ks+1][2], s[2*ks+1][3]) };
#pragma unroll
            for (int dp = 0; dp < 4; dp++) {
                const int grp = lane >> 3;
                const uint32_t vaddr = kvb + 36864
                                     + (ks * 16 + (grp & 1) * 8 + (lane & 7)) * AT_STRIDE
                                     + dp * 32 + (grp >> 1) * 16;
                uint32_t vfh[4];
                ldm4t(vfh, vaddr);
                mma_bf16(accO[dp * 2 + 0], pah, vfh + 0);
                mma_bf16(accO[dp * 2 + 1], pah, vfh + 2);
            }
        }
        if (kc + 1 < SEQ / 128) __syncthreads();
    }

    const float inv0 = 1.f / l0, inv1 = 1.f / l1;
    const int s0 = qt * 128 + w * 16 + g;
    const size_t r0 = ((size_t)b * SEQ + s0) * EMB + h * DK;
    const size_t r1 = ((size_t)b * SEQ + s0 + 8) * EMB + h * DK;
#pragma unroll
    for (int dnb = 0; dnb < 8; dnb++) {
        const int col = dnb * 8 + c4 * 2;
        float v0 = accO[dnb][0] * inv0, v1 = accO[dnb][1] * inv0;
        float v2 = accO[dnb][2] * inv1, v3 = accO[dnb][3] * inv1;
        __nv_bfloat16 h0 = __float2bfloat16(v0), h1 = __float2bfloat16(v1);
        __nv_bfloat16 h2 = __float2bfloat16(v2), h3 = __float2bfloat16(v3);
        *(uint32_t*)(Oh + r0 + col) = ((uint32_t)__bfloat16_as_ushort(h1) << 16) | __bfloat16_as_ushort(h0);
        *(uint32_t*)(Oh + r1 + col) = ((uint32_t)__bfloat16_as_ushort(h3) << 16) | __bfloat16_as_ushort(h2);
        __nv_bfloat16 q0 = __float2bfloat16(v0 - __bfloat162float(h0));
        __nv_bfloat16 q1 = __float2bfloat16(v1 - __bfloat162float(h1));
        __nv_bfloat16 q2 = __float2bfloat16(v2 - __bfloat162float(h2));
        __nv_bfloat16 q3 = __float2bfloat16(v3 - __bfloat162float(h3));
        *(uint32_t*)(Ol + r0 + col) = ((uint32_t)__bfloat16_as_ushort(q1) << 16) | __bfloat16_as_ushort(q0);
        *(uint32_t*)(Ol + r1 + col) = ((uint32_t)__bfloat16_as_ushort(q3) << 16) | __bfloat16_as_ushort(q2);
    }
}

// ==================== launch ====================
extern "C" void kernel_launch(void* const* d_in, const int* in_sizes, int n_in,
                              void* d_out, int out_size) {
    const float* x    = (const float*)d_in[0];
    const int*   mask = (const int*)  d_in[1];
    const float* wq   = (const float*)d_in[2];
    const float* wk   = (const float*)d_in[3];
    const float* wv   = (const float*)d_in[4];
    const float* wo   = (const float*)d_in[5];
    const float* ff1w = (const float*)d_in[6];
    const float* ff1b = (const float*)d_in[7];
    const float* ff2w = (const float*)d_in[8];
    const float* ff2b = (const float*)d_in[9];
    const float* ln1a = (const float*)d_in[10];
    const float* ln1b = (const float*)d_in[11];
    const float* ln2a = (const float*)d_in[12];
    const float* ln2b = (const float*)d_in[13];
    float* out = (float*)d_out;

    float *hb;
    __nv_bfloat16 *lnh, *lnl, *qkvh, *qkvl, *ath, *atl, *ffh, *ffl;
    __nv_bfloat16 *wqkvh, *wqkvl, *woh, *wol, *f1h, *f1l, *f2h, *f2l;
    cudaGetSymbolAddress((void**)&hb, g_h);
    cudaGetSymbolAddress((void**)&lnh, g_lnh);
    cudaGetSymbolAddress((void**)&lnl, g_lnl);
    cudaGetSymbolAddress((void**)&qkvh, g_qkvh);
    cudaGetSymbolAddress((void**)&qkvl, g_qkvl);
    cudaGetSymbolAddress((void**)&ath, g_ath);
    cudaGetSymbolAddress((void**)&atl, g_atl);
    cudaGetSymbolAddress((void**)&ffh, g_ffh);
    cudaGetSymbolAddress((void**)&ffl, g_ffl);
    cudaGetSymbolAddress((void**)&wqkvh, g_wqkvh);
    cudaGetSymbolAddress((void**)&wqkvl, g_wqkvl);
    cudaGetSymbolAddress((void**)&woh, g_woh); cudaGetSymbolAddress((void**)&wol, g_wol);
    cudaGetSymbolAddress((void**)&f1h, g_f1h); cudaGetSymbolAddress((void**)&f1l, g_f1l);
    cudaGetSymbolAddress((void**)&f2h, g_f2h); cudaGetSymbolAddress((void**)&f2l, g_f2l);

    cudaFuncSetAttribute(mgemm_kernel<EPI_QKV>,             cudaFuncAttributeMaxDynamicSharedMemorySize, MGEMM_SMEM);
    cudaFuncSetAttribute(mgemm_kernel<EPI_RES>,             cudaFuncAttributeMaxDynamicSharedMemorySize, MGEMM_SMEM);
    cudaFuncSetAttribute(mgemm_kernel<EPI_BIAS_RELU_SPLIT>, cudaFuncAttributeMaxDynamicSharedMemorySize, MGEMM_SMEM);
    cudaFuncSetAttribute(mgemm_kernel<EPI_BIAS_RES>,        cudaFuncAttributeMaxDynamicSharedMemorySize, MGEMM_SMEM);
    cudaFuncSetAttribute(attn3_kernel,                      cudaFuncAttributeMaxDynamicSharedMemorySize, ATT_SMEM);

    dim3 tb(32, 8);
    splitT_qkv_kernel<<<dim3(32, 32, 3), tb>>>(wq, wk, wv, wqkvh, wqkvl);
    splitT_kernel<<<dim3(32, 32), tb>>>(wo, woh, wol, EMB, EMB);
    splitT_kernel<<<dim3(128, 32), tb>>>(ff1w, f1h, f1l, EMB, HID);
    splitT_kernel<<<dim3(32, 128), tb>>>(ff2w, f2h, f2l, HID, EMB);
    ln_kernel<<<ROWS, 256>>>(x, lnh, lnl, ln1a, ln1b);

    dim3 gQKV(3 * EMB / 128, ROWS / 128); // (24,32)
    dim3 gP(EMB / 128, ROWS / 128);       // (8,32)
    dim3 gF(HID / 128, ROWS / 128);       // (32,32)

    mgemm_kernel<EPI_QKV><<<gQKV, 256, MGEMM_SMEM>>>(lnh, lnl, wqkvh, wqkvl, EMB, 3*EMB, nullptr, nullptr, nullptr, qkvh, qkvl);
    attn3_kernel<<<dim3(SEQ / 128, BATCH * NHEADS), 256, ATT_SMEM>>>(qkvh, qkvl, mask, ath, atl);
    mgemm_kernel<EPI_RES><<<gP, 256, MGEMM_SMEM>>>(ath, atl, woh, wol, EMB, EMB, hb, nullptr, x, nullptr, nullptr);
    ln_kernel<<<ROWS, 256>>>(hb, lnh, lnl, ln2a, ln2b);
    mgemm_kernel<EPI_BIAS_RELU_SPLIT><<<gF, 256, MGEMM_SMEM>>>(lnh, lnl, f1h, f1l, EMB, HID, nullptr, ff1b, nullptr, ffh, ffl);
    mgemm_kernel<EPI_BIAS_RES><<<gP, 256, MGEMM_SMEM>>>(ffh, ffl, f2h, f2l, HID, EMB, out, ff2b, hb, nullptr, nullptr);
}